// round 9
// baseline (speedup 1.0000x reference)
#include <cuda_runtime.h>
#include <cuda_bf16.h>
#include <cuda/atomic>

// Problem constants (fixed by the reference setup_inputs)
#define BATCH      16
#define HW         512
#define MCOMP      200000
#define NTHR       256
#define RPT        8                         // records per thread
#define CHUNK_REC  (RPT * NTHR)              // 2048 records per block
#define MAXCHUNKB  ((MCOMP + CHUNK_REC - 1) / CHUNK_REC)   // 98
#define MAXCHUNKS  (BATCH * MAXCHUNKB)       // 1568

#define EPS_F   1e-10f
#define THR_F   1.1f            // 1.0 + DELTA

// Scratch: per-chunk partial sums (sum_w, sum_w*mismatch) + completion counter
__device__ float2 g_part[MAXCHUNKS];
__device__ unsigned int g_count;   // zero-init; reset by last block each run

__device__ __forceinline__ void whdr_eval(float x1f, float y1f, float x2f, float y2f,
                                          float darkerf, float w,
                                          const float* __restrict__ img,
                                          float& ws, float& wm)
{
    const int x1 = (int)x1f, y1 = (int)y1f;
    const int x2 = (int)x2f, y2 = (int)y2f;
    const int darker = (int)darkerf;

    const float r1 = __ldg(img + y1 * HW + x1);
    const float r2 = __ldg(img + y2 * HW + x2);

    // alg = 1 if r2/(r1+eps) > thr ; 2 if r1/(r2+eps) > thr ; else 0
    int alg = 0;
    if (r2 > THR_F * (r1 + EPS_F))      alg = 1;
    else if (r1 > THR_F * (r2 + EPS_F)) alg = 2;

    ws += w;
    if (alg != darker) wm += w;
}

__global__ __launch_bounds__(NTHR)
void whdr_kernel(const float* __restrict__ v_input,
                 const float* __restrict__ comparisons,
                 const int*   __restrict__ numComparisons,
                 float* __restrict__ out)
{
    __shared__ int s_n[BATCH];
    __shared__ int s_coff[BATCH + 1];   // chunk-offset prefix per batch

    const int tid  = threadIdx.x;
    const int lane = tid & 31;
    const int warp = tid >> 5;

    if (tid < BATCH) s_n[tid] = numComparisons[tid];
    __syncthreads();
    if (tid == 0) {
        int acc = 0;
        s_coff[0] = 0;
        #pragma unroll
        for (int i = 0; i < BATCH; i++) {
            acc += (s_n[i] + CHUNK_REC - 1) / CHUNK_REC;
            s_coff[i + 1] = acc;
        }
    }
    __syncthreads();

    const int c = blockIdx.x;
    const int total_chunks = s_coff[BATCH];

    float ws = 0.0f, wm = 0.0f;

    if (c < total_chunks) {
        // find batch of this chunk
        int b = 0;
        #pragma unroll
        for (int i = 1; i < BATCH; i++) b += (c >= s_coff[i]);

        const int nb = s_n[b];
        const int sp = (c - s_coff[b]) * CHUNK_REC;

        const float* __restrict__ img = v_input + (size_t)b * HW * HW;
        const float2* __restrict__ c2 =
            (const float2*)(comparisons + (size_t)b * MCOMP * 6);

        // Two groups of 4 records: 12 float2 streaming loads + up to 8 gathers
        // in flight per group (plain evict-normal loads — proven R2 path).
        #pragma unroll
        for (int g = 0; g < 2; g++) {
            float2 r0[4], r1[4], r2v[4];
            float  msk[4];
            #pragma unroll
            for (int i = 0; i < 4; i++) {
                const int m  = sp + tid + (g * 4 + i) * NTHR;
                const bool v = m < nb;
                const int mc = v ? m : 0;            // clamp: safe dummy record
                r0[i]  = c2[(size_t)mc * 3 + 0];     // (x1, y1)
                r1[i]  = c2[(size_t)mc * 3 + 1];     // (x2, y2)
                r2v[i] = c2[(size_t)mc * 3 + 2];     // (darker, weight)
                msk[i] = v ? 1.0f : 0.0f;
            }
            #pragma unroll
            for (int i = 0; i < 4; i++) {
                whdr_eval(r0[i].x, r0[i].y, r1[i].x, r1[i].y,
                          r2v[i].x, r2v[i].y * msk[i], img, ws, wm);
            }
        }
    }

    // block reduction (8 warps)
    __shared__ float s_ws[NTHR / 32];
    __shared__ float s_wm[NTHR / 32];
    #pragma unroll
    for (int o = 16; o > 0; o >>= 1) {
        ws += __shfl_down_sync(0xFFFFFFFFu, ws, o);
        wm += __shfl_down_sync(0xFFFFFFFFu, wm, o);
    }
    if (lane == 0) { s_ws[warp] = ws; s_wm[warp] = wm; }
    __syncthreads();

    __shared__ bool s_last;
    if (warp == 0) {
        ws = (lane < NTHR / 32) ? s_ws[lane] : 0.0f;
        wm = (lane < NTHR / 32) ? s_wm[lane] : 0.0f;
        #pragma unroll
        for (int o = 4; o > 0; o >>= 1) {
            ws += __shfl_down_sync(0xFFFFFFFFu, ws, o);
            wm += __shfl_down_sync(0xFFFFFFFFu, wm, o);
        }
        if (lane == 0) {
            // Publish partial straight to L2 (write-through, bypass L1),
            // then RELEASE-only counter bump. Release orders our prior
            // writes without an L1 invalidate — no CCTL.IVALL per block
            // (the acquire side is what flushes; we do that ONCE below).
            __stcg(&g_part[c], make_float2(ws, wm));
            cuda::atomic_ref<unsigned int, cuda::thread_scope_device> cnt(g_count);
            unsigned int prev = cnt.fetch_add(1u, cuda::memory_order_release);
            s_last = (prev == (unsigned int)(gridDim.x - 1));
        }
    }
    __syncthreads();

    // Last block: single acquire fence (one IVALL on one SM, after all its
    // gather work is done), then deterministic per-batch final reduction.
    if (s_last) {
        cuda::atomic_thread_fence(cuda::memory_order_acquire,
                                  cuda::thread_scope_device);
        __shared__ float s_per[BATCH];
        // 8 warps, each handles 2 batches; lane-strided over that batch's chunks
        #pragma unroll
        for (int t = 0; t < 2; t++) {
            const int bb  = warp * 2 + t;
            const int lo  = s_coff[bb];
            const int hi  = s_coff[bb + 1];
            float fws = 0.0f, fwm = 0.0f;
            for (int k = lo + lane; k < hi; k += 32) {
                const float2 p = __ldcg(&g_part[k]);
                fws += p.x;
                fwm += p.y;
            }
            #pragma unroll
            for (int o = 16; o > 0; o >>= 1) {
                fws += __shfl_down_sync(0xFFFFFFFFu, fws, o);
                fwm += __shfl_down_sync(0xFFFFFFFFu, fwm, o);
            }
            if (lane == 0) s_per[bb] = fwm / fws;
        }
        __syncthreads();
        if (tid == 0) {
            float s = 0.0f;
            #pragma unroll
            for (int i = 0; i < BATCH; i++) s += s_per[i];
            out[0] = s * (1.0f / BATCH);
            g_count = 0;   // self-reset for next graph replay
        }
    }
}

extern "C" void kernel_launch(void* const* d_in, const int* in_sizes, int n_in,
                              void* d_out, int out_size)
{
    const float* v_input        = (const float*)d_in[0];
    const float* comparisons    = (const float*)d_in[1];
    const int*   numComparisons = (const int*)  d_in[2];
    float* out = (float*)d_out;

    whdr_kernel<<<MAXCHUNKS, NTHR>>>(v_input, comparisons, numComparisons, out);
}